// round 13
// baseline (speedup 1.0000x reference)
#include <cuda_runtime.h>
#include <cuda_fp16.h>

#define BATCH 1024
#define LOG2E 1.4426950408889634f

// ---------------- device scratch (no allocations allowed) ----------------
__device__ float g_h2[BATCH * 128];    // after layer 2 (pre-BN)
__device__ float g_sum[128];           // per-col sum of h2 (zeroed by k4 tail)
__device__ float g_sq[128];            // per-col sum of h2^2
__device__ uint4 g_Mh[50 * BATCH];     // M * log2e as 5 halfs (+pad), f-major

__device__ __forceinline__ float lrelu(float v) { return fmaxf(v, 0.2f * v); }

// ---- K12: fused  h1 = lrelu(x@W1+b1) ;  h2 = h1@W2+b2  (+ BN partials) ---
// 4 rows/block, 256 threads, grid 256. LDG.128 weight streaming with an
// EXPLICIT 8-deep register prefetch ring (manual software pipeline), K split
// across thread groups, partials combined via smem.
__global__ void __launch_bounds__(256, 2) k12_gemm(const float* __restrict__ x,
                                                   const float* __restrict__ W1,
                                                   const float* __restrict__ b1,
                                                   const float* __restrict__ W2,
                                                   const float* __restrict__ b2) {
    __shared__ float  xs[4][128];
    __shared__ float  h1s[4][256];
    __shared__ float4 part[1024];      // 16KB scratch, reused by both stages
    const int t  = threadIdx.x;
    const int r0 = blockIdx.x * 4;

    for (int n = t; n < 512; n += 256)
        xs[n >> 7][n & 127] = x[(r0 + (n >> 7)) * 128 + (n & 127)];

    // ================= stage 1: h1 = lrelu(x @ W1 + b1) ==================
    // thread -> (kgroup ks of 4 x 32 k's, colgroup cg of 64 x 4 cols),
    // computes partials for ALL 4 rows.
    {
        const int cg = t & 63, ks = t >> 6, kb = ks * 32;
        const float4* __restrict__ W1v = (const float4*)W1;
        float4 wbuf[8];
#pragma unroll
        for (int i = 0; i < 8; i++) wbuf[i] = W1v[(kb + i) * 64 + cg];
        __syncthreads();   // xs ready

        float4 a0 = {0,0,0,0}, a1 = {0,0,0,0}, a2 = {0,0,0,0}, a3 = {0,0,0,0};
#pragma unroll
        for (int k = 0; k < 32; k++) {
            const float4 w = wbuf[k & 7];
            if (k < 24) wbuf[k & 7] = W1v[(kb + k + 8) * 64 + cg];
            const float x0 = xs[0][kb + k], x1 = xs[1][kb + k];
            const float x2 = xs[2][kb + k], x3 = xs[3][kb + k];
            a0.x = fmaf(x0, w.x, a0.x); a0.y = fmaf(x0, w.y, a0.y);
            a0.z = fmaf(x0, w.z, a0.z); a0.w = fmaf(x0, w.w, a0.w);
            a1.x = fmaf(x1, w.x, a1.x); a1.y = fmaf(x1, w.y, a1.y);
            a1.z = fmaf(x1, w.z, a1.z); a1.w = fmaf(x1, w.w, a1.w);
            a2.x = fmaf(x2, w.x, a2.x); a2.y = fmaf(x2, w.y, a2.y);
            a2.z = fmaf(x2, w.z, a2.z); a2.w = fmaf(x2, w.w, a2.w);
            a3.x = fmaf(x3, w.x, a3.x); a3.y = fmaf(x3, w.y, a3.y);
            a3.z = fmaf(x3, w.z, a3.z); a3.w = fmaf(x3, w.w, a3.w);
        }
        part[(ks * 4 + 0) * 64 + cg] = a0;
        part[(ks * 4 + 1) * 64 + cg] = a1;
        part[(ks * 4 + 2) * 64 + cg] = a2;
        part[(ks * 4 + 3) * 64 + cg] = a3;
    }
    __syncthreads();

    // combine stage-1 partials: thread -> (row rr, colgroup cc)
    {
        const int cc = t & 63, rr = t >> 6;
        float4 s = part[(0 * 4 + rr) * 64 + cc];
#pragma unroll
        for (int g = 1; g < 4; g++) {
            const float4 p = part[(g * 4 + rr) * 64 + cc];
            s.x += p.x; s.y += p.y; s.z += p.z; s.w += p.w;
        }
        const float4 bb = ((const float4*)b1)[cc];
        *(float4*)&h1s[rr][cc * 4] =
            make_float4(lrelu(s.x + bb.x), lrelu(s.y + bb.y),
                        lrelu(s.z + bb.z), lrelu(s.w + bb.w));
    }
    __syncthreads();   // h1s ready AND part free for stage 2

    // ================= stage 2: h2 = h1 @ W2 + b2 ========================
    // thread -> (kgroup ks2 of 8 x 32 k's, colgroup cg2 of 32 x 4 cols)
    {
        const int cg2 = t & 31, ks2 = t >> 5, kb = ks2 * 32;
        const float4* __restrict__ W2v = (const float4*)W2;
        float4 wbuf[8];
#pragma unroll
        for (int i = 0; i < 8; i++) wbuf[i] = W2v[(kb + i) * 32 + cg2];

        float4 a0 = {0,0,0,0}, a1 = {0,0,0,0}, a2 = {0,0,0,0}, a3 = {0,0,0,0};
#pragma unroll
        for (int k = 0; k < 32; k++) {
            const float4 w = wbuf[k & 7];
            if (k < 24) wbuf[k & 7] = W2v[(kb + k + 8) * 32 + cg2];
            const float h0 = h1s[0][kb + k], h1 = h1s[1][kb + k];
            const float h2 = h1s[2][kb + k], h3 = h1s[3][kb + k];
            a0.x = fmaf(h0, w.x, a0.x); a0.y = fmaf(h0, w.y, a0.y);
            a0.z = fmaf(h0, w.z, a0.z); a0.w = fmaf(h0, w.w, a0.w);
            a1.x = fmaf(h1, w.x, a1.x); a1.y = fmaf(h1, w.y, a1.y);
            a1.z = fmaf(h1, w.z, a1.z); a1.w = fmaf(h1, w.w, a1.w);
            a2.x = fmaf(h2, w.x, a2.x); a2.y = fmaf(h2, w.y, a2.y);
            a2.z = fmaf(h2, w.z, a2.z); a2.w = fmaf(h2, w.w, a2.w);
            a3.x = fmaf(h3, w.x, a3.x); a3.y = fmaf(h3, w.y, a3.y);
            a3.z = fmaf(h3, w.z, a3.z); a3.w = fmaf(h3, w.w, a3.w);
        }
        part[(ks2 * 4 + 0) * 32 + cg2] = a0;
        part[(ks2 * 4 + 1) * 32 + cg2] = a1;
        part[(ks2 * 4 + 2) * 32 + cg2] = a2;
        part[(ks2 * 4 + 3) * 32 + cg2] = a3;
    }
    __syncthreads();

    // combine stage-2 partials: 128 threads -> (row r, colgroup c)
    if (t < 128) {
        const int c = t & 31, r = t >> 5;
        float4 s = part[(0 * 4 + r) * 32 + c];
#pragma unroll
        for (int g = 1; g < 8; g++) {
            const float4 p = part[(g * 4 + r) * 32 + c];
            s.x += p.x; s.y += p.y; s.z += p.z; s.w += p.w;
        }
        const float4 bb = ((const float4*)b2)[c];
        const float4 v = make_float4(s.x + bb.x, s.y + bb.y, s.z + bb.z, s.w + bb.w);
        const int c0 = c * 4;
        *(float4*)&g_h2[(r0 + r) * 128 + c0] = v;
        atomicAdd(&g_sum[c0 + 0], v.x);
        atomicAdd(&g_sum[c0 + 1], v.y);
        atomicAdd(&g_sum[c0 + 2], v.z);
        atomicAdd(&g_sum[c0 + 3], v.w);
        atomicAdd(&g_sq[c0 + 0], v.x * v.x);
        atomicAdd(&g_sq[c0 + 1], v.y * v.y);
        atomicAdd(&g_sq[c0 + 2], v.z * v.z);
        atomicAdd(&g_sq[c0 + 3], v.w * v.w);
    }
}

// ---- K3: BN+lrelu -> layer3 -> attention -> M (fp16, pre-scaled) --------
__global__ void __launch_bounds__(256, 2) k3_feat(const float* __restrict__ gamma,
                                                  const float* __restrict__ beta,
                                                  const float* __restrict__ W3,
                                                  const float* __restrict__ b3,
                                                  const float* __restrict__ Wv,
                                                  const float* __restrict__ bv,
                                                  const float* __restrict__ Wo,
                                                  const float* __restrict__ bo,
                                                  const float* __restrict__ T,
                                                  const float* __restrict__ Ws,
                                                  const float* __restrict__ bs,
                                                  float* __restrict__ out) {
    __shared__ float hb[8][128], h3s[8][64], avs[8][64], hhs[8][64];
    __shared__ float Mst[8][250];
    const int t  = threadIdx.x;
    const int r0 = blockIdx.x * 8;

#pragma unroll
    for (int qq = 0; qq < 4; qq++) {
        const int e = t + 256 * qq;
        const int r = e >> 7, c = e & 127;
        const float v   = g_h2[(r0 + r) * 128 + c];
        const float mu  = g_sum[c] * (1.f / BATCH);
        const float var = g_sq[c] * (1.f / BATCH) - mu * mu;
        const float rs  = rsqrtf(var + 1e-5f);
        hb[r][c] = lrelu(fmaf((v - mu) * rs, gamma[c], beta[c]));
    }
    __syncthreads();

    const int c  = t & 63;
    const int rg = t >> 6;               // 4 groups x 2 rows
    {
        float a0 = b3[c], a1 = a0;
#pragma unroll 16
        for (int k = 0; k < 128; k++) {
            const float w = W3[k * 64 + c];
            a0 = fmaf(hb[2 * rg][k], w, a0);
            a1 = fmaf(hb[2 * rg + 1][k], w, a1);
        }
        h3s[2 * rg][c] = lrelu(a0);
        h3s[2 * rg + 1][c] = lrelu(a1);
    }
    __syncthreads();
    {
        float a0 = bv[c], a1 = a0;
#pragma unroll 16
        for (int k = 0; k < 64; k++) {
            const float w = Wv[k * 64 + c];
            a0 = fmaf(h3s[2 * rg][k], w, a0);
            a1 = fmaf(h3s[2 * rg + 1][k], w, a1);
        }
        avs[2 * rg][c] = a0;
        avs[2 * rg + 1][c] = a1;
    }
    __syncthreads();
    {
        float a0 = bo[c] + h3s[2 * rg][c];
        float a1 = bo[c] + h3s[2 * rg + 1][c];
#pragma unroll 16
        for (int k = 0; k < 64; k++) {
            const float w = Wo[k * 64 + c];
            a0 = fmaf(avs[2 * rg][k], w, a0);
            a1 = fmaf(avs[2 * rg + 1][k], w, a1);
        }
        hhs[2 * rg][c] = a0;
        hhs[2 * rg + 1][c] = a1;
    }
    __syncthreads();

    {   // score base: one warp per row
        const int r = t >> 5, l = t & 31;
        float v = hhs[r][l] * Ws[l] + hhs[r][l + 32] * Ws[l + 32];
#pragma unroll
        for (int o = 16; o > 0; o >>= 1) v += __shfl_down_sync(0xffffffffu, v, o);
        if (l == 0) out[r0 + r] = v + bs[0];
    }

    if (t < 250) {                       // M = hh @ T (pre-scaled by log2 e)
        float acc[8];
#pragma unroll
        for (int r = 0; r < 8; r++) acc[r] = 0.f;
#pragma unroll 8
        for (int k = 0; k < 64; k++) {
            const float w = T[k * 250 + t];
#pragma unroll
            for (int r = 0; r < 8; r++) acc[r] = fmaf(hhs[r][k], w, acc[r]);
        }
#pragma unroll
        for (int r = 0; r < 8; r++) Mst[r][t] = acc[r] * LOG2E;
    }
    __syncthreads();

    for (int idx = t; idx < 400; idx += 256) {
        const int r = idx / 50, f = idx % 50;
        __half2 h01 = __floats2half2_rn(Mst[r][5 * f + 0], Mst[r][5 * f + 1]);
        __half2 h23 = __floats2half2_rn(Mst[r][5 * f + 2], Mst[r][5 * f + 3]);
        __half2 h4p = __floats2half2_rn(Mst[r][5 * f + 4], 0.f);
        uint4 v;
        v.x = *reinterpret_cast<const unsigned*>(&h01);
        v.y = *reinterpret_cast<const unsigned*>(&h23);
        v.z = *reinterpret_cast<const unsigned*>(&h4p);
        v.w = 0u;
        g_Mh[f * BATCH + r0 + r] = v;
    }
}

// ------- K4: MBD, symmetric pairs, fp16x2 v2 + vectorized LDS ------------
__global__ void __launch_bounds__(256) k4_mbd(const float* __restrict__ Ws,
                                              float* __restrict__ out) {
    __shared__ __align__(16) __half2 sA[10][5][64];  // (m,m) broadcast pairs
    __shared__ __align__(16) __half  sJ[10][5][64];  // plain halves by j
    __shared__ float red[16][132];

    const int t = threadIdx.x;
    int u = blockIdx.x, ti_s = 0;
    while (u >= 16 - ti_s) { u -= 16 - ti_s; ti_s++; }
    const int tj_s = ti_s + u;
    const int I0 = ti_s * 64, J0 = tj_s * 64;
    const bool diag = (ti_s == tj_s);
    const int ti = t >> 4, tj = t & 15;

    const uint4* __restrict__ Mh = g_Mh + blockIdx.y * 10 * BATCH;
    for (int idx = t; idx < 640; idx += 256) {
        const int ff = idx >> 6, r = idx & 63;
        const uint4 vI = Mh[ff * BATCH + I0 + r];
        const __half2 a01 = *reinterpret_cast<const __half2*>(&vI.x);
        const __half2 a23 = *reinterpret_cast<const __half2*>(&vI.y);
        const __half2 a4  = *reinterpret_cast<const __half2*>(&vI.z);
        sA[ff][0][r] = __half2half2(__low2half(a01));
        sA[ff][1][r] = __half2half2(__high2half(a01));
        sA[ff][2][r] = __half2half2(__low2half(a23));
        sA[ff][3][r] = __half2half2(__high2half(a23));
        sA[ff][4][r] = __half2half2(__low2half(a4));
        const uint4 vJ = Mh[ff * BATCH + J0 + r];
        const __half2 j01 = *reinterpret_cast<const __half2*>(&vJ.x);
        const __half2 j23 = *reinterpret_cast<const __half2*>(&vJ.y);
        const __half2 j4  = *reinterpret_cast<const __half2*>(&vJ.z);
        sJ[ff][0][r] = __low2half(j01);
        sJ[ff][1][r] = __high2half(j01);
        sJ[ff][2][r] = __low2half(j23);
        sJ[ff][3][r] = __high2half(j23);
        sJ[ff][4][r] = __low2half(j4);
    }
    __syncthreads();

    // diag lane masks: allowed iff local i > local j (I0 == J0 on diag)
    __half2 dmask[4][2];
#pragma unroll
    for (int a = 0; a < 4; a++)
#pragma unroll
        for (int bp = 0; bp < 2; bp++)
            dmask[a][bp] = __floats2half2_rn(
                (ti * 4 + a) > (tj * 4 + 2 * bp) ? 1.f : 0.f,
                (ti * 4 + a) > (tj * 4 + 2 * bp + 1) ? 1.f : 0.f);

    float raccW[4] = {0.f, 0.f, 0.f, 0.f};
    float caccW[4] = {0.f, 0.f, 0.f, 0.f};

#pragma unroll 1
    for (int ff = 0; ff < 10; ff++) {
        __half2 mA[4][5], mJ[2][5];
#pragma unroll
        for (int d = 0; d < 5; d++) {
            const uint4 va = *reinterpret_cast<const uint4*>(&sA[ff][d][ti * 4]);
            mA[0][d] = *reinterpret_cast<const __half2*>(&va.x);
            mA[1][d] = *reinterpret_cast<const __half2*>(&va.y);
            mA[2][d] = *reinterpret_cast<const __half2*>(&va.z);
            mA[3][d] = *reinterpret_cast<const __half2*>(&va.w);
            const uint2 vj = *reinterpret_cast<const uint2*>(&sJ[ff][d][tj * 4]);
            mJ[0][d] = *reinterpret_cast<const __half2*>(&vj.x);
            mJ[1][d] = *reinterpret_cast<const __half2*>(&vj.y);
        }

        __half2 racc2[4], cacc2[2];
#pragma unroll
        for (int a = 0; a < 4; a++) racc2[a] = __floats2half2_rn(0.f, 0.f);
#pragma unroll
        for (int bp = 0; bp < 2; bp++) cacc2[bp] = __floats2half2_rn(0.f, 0.f);

        if (!diag) {
#pragma unroll
            for (int a = 0; a < 4; a++) {
#pragma unroll
                for (int bp = 0; bp < 2; bp++) {
                    const __half2 d0 = __hsub2(mA[a][0], mJ[bp][0]);
                    const __half2 d1 = __hsub2(mA[a][1], mJ[bp][1]);
                    const __half2 d2 = __hsub2(mA[a][2], mJ[bp][2]);
                    const __half2 d3 = __hsub2(mA[a][3], mJ[bp][3]);
                    const __half2 d4 = __hsub2(mA[a][4], mJ[bp][4]);
                    __half2 s = __hadd2(__habs2(d0), __habs2(d1));
                    const __half2 s2 = __hadd2(__habs2(d2), __habs2(d3));
                    s = __hadd2(s, s2);
                    s = __hadd2(s, __habs2(d4));
                    const __half2 e = h2exp2(__hneg2(s));
                    racc2[a]  = __hadd2(racc2[a], e);
                    cacc2[bp] = __hadd2(cacc2[bp], e);
                }
            }
        } else {
#pragma unroll
            for (int a = 0; a < 4; a++) {
#pragma unroll
                for (int bp = 0; bp < 2; bp++) {
                    const __half2 d0 = __hsub2(mA[a][0], mJ[bp][0]);
                    const __half2 d1 = __hsub2(mA[a][1], mJ[bp][1]);
                    const __half2 d2 = __hsub2(mA[a][2], mJ[bp][2]);
                    const __half2 d3 = __hsub2(mA[a][3], mJ[bp][3]);
                    const __half2 d4 = __hsub2(mA[a][4], mJ[bp][4]);
                    __half2 s = __hadd2(__habs2(d0), __habs2(d1));
                    const __half2 s2 = __hadd2(__habs2(d2), __habs2(d3));
                    s = __hadd2(s, s2);
                    s = __hadd2(s, __habs2(d4));
                    __half2 e = h2exp2(__hneg2(s));
                    e = __hmul2(e, dmask[a][bp]);
                    racc2[a]  = __hadd2(racc2[a], e);
                    cacc2[bp] = __hadd2(cacc2[bp], e);
                }
            }
        }
        const float wf = Ws[64 + blockIdx.y * 10 + ff];
#pragma unroll
        for (int a = 0; a < 4; a++) {
            const float2 fr = __half22float2(racc2[a]);
            raccW[a] = fmaf(fr.x + fr.y, wf, raccW[a]);
        }
#pragma unroll
        for (int bp = 0; bp < 2; bp++) {
            const float2 fc = __half22float2(cacc2[bp]);
            caccW[2 * bp]     = fmaf(fc.x, wf, caccW[2 * bp]);
            caccW[2 * bp + 1] = fmaf(fc.y, wf, caccW[2 * bp + 1]);
        }
    }

    __syncthreads();
#pragma unroll
    for (int a = 0; a < 4; a++) red[tj][ti * 4 + a] = raccW[a];
#pragma unroll
    for (int b = 0; b < 4; b++) red[ti][64 + tj * 4 + b] = caccW[b];
    __syncthreads();

    if (t < 128) {
        float s = 0.f;
#pragma unroll
        for (int g = 0; g < 16; g++) s += red[g][t];
        const int target = (t < 64) ? (I0 + t) : (J0 + t - 64);
        atomicAdd(&out[target], s);
    }

    // re-zero BN stat accumulators for the NEXT graph replay (k4 is the
    // final node; next replay's k12 follows it in stream order).
    if (blockIdx.x == 0 && blockIdx.y == 0 && t < 128) {
        g_sum[t] = 0.f;
        g_sq[t]  = 0.f;
    }
}

// ---------------- launcher ----------------
extern "C" void kernel_launch(void* const* d_in, const int* in_sizes, int n_in,
                              void* d_out, int out_size) {
    const float* x     = (const float*)d_in[0];
    const float* W1    = (const float*)d_in[1];
    const float* b1    = (const float*)d_in[2];
    const float* W2    = (const float*)d_in[3];
    const float* b2    = (const float*)d_in[4];
    const float* gamma = (const float*)d_in[5];
    const float* beta  = (const float*)d_in[6];
    const float* W3    = (const float*)d_in[7];
    const float* b3    = (const float*)d_in[8];
    const float* Wv    = (const float*)d_in[9];
    const float* bv    = (const float*)d_in[10];
    const float* Wo    = (const float*)d_in[11];
    const float* bo    = (const float*)d_in[12];
    const float* T     = (const float*)d_in[13];
    const float* Ws    = (const float*)d_in[14];
    const float* bs    = (const float*)d_in[15];
    float* out = (float*)d_out;

    k12_gemm<<<256, 256>>>(x, W1, b1, W2, b2);
    k3_feat<<<128, 256>>>(gamma, beta, W3, b3, Wv, bv, Wo, bo, T, Ws, bs, out);
    k4_mbd<<<dim3(136, 5), 256>>>(Ws, out);
}

// round 14
// speedup vs baseline: 1.8838x; 1.8838x over previous
#include <cuda_runtime.h>
#include <cuda_fp16.h>

#define BATCH 1024
#define LOG2E 1.4426950408889634f

// ---------------- device scratch (no allocations allowed) ----------------
__device__ float g_h2[BATCH * 128];    // after layer 2 (pre-BN)
__device__ float g_sum[128];           // per-col sum of h2 (zeroed by k4 tail)
__device__ float g_sq[128];            // per-col sum of h2^2
__device__ uint4 g_Mh[50 * BATCH];     // M * log2e as 5 halfs (+pad), f-major

__device__ __forceinline__ float lrelu(float v) { return fmaxf(v, 0.2f * v); }

// ---- K12: fused  h1 = lrelu(x@W1+b1) ;  h2 = h1@W2+b2  (+ BN partials) ---
// 4 rows/block, 256 threads, grid 256. Scalar weight streaming, unroll 16,
// reg cap 128 (proven R12 pattern). Stage 2 is K-SPLIT: thread = (col, k-half),
// all 4 rows, so every W2 element is loaded exactly once per block.
__global__ void __launch_bounds__(256, 2) k12_gemm(const float* __restrict__ x,
                                                   const float* __restrict__ W1,
                                                   const float* __restrict__ b1,
                                                   const float* __restrict__ W2,
                                                   const float* __restrict__ b2) {
    __shared__ float xs[4][128];
    __shared__ float h1s[4][256];
    __shared__ float p2[4][128];       // stage-2 partials (k-half 1)
    const int t  = threadIdx.x;
    const int r0 = blockIdx.x * 4;

    for (int n = t; n < 512; n += 256)
        xs[n >> 7][n & 127] = x[(r0 + (n >> 7)) * 128 + (n & 127)];
    __syncthreads();

    // ---- stage 1: thread t owns column t (of 256), all 4 rows ----
    {
        float acc[4] = {0.f, 0.f, 0.f, 0.f};
#pragma unroll 16
        for (int k4 = 0; k4 < 128; k4 += 4) {
            const float w0 = W1[(k4 + 0) * 256 + t];
            const float w1 = W1[(k4 + 1) * 256 + t];
            const float w2 = W1[(k4 + 2) * 256 + t];
            const float w3 = W1[(k4 + 3) * 256 + t];
#pragma unroll
            for (int r = 0; r < 4; r++) {
                const float4 xv = *(const float4*)&xs[r][k4];
                acc[r] = fmaf(xv.x, w0, acc[r]);
                acc[r] = fmaf(xv.y, w1, acc[r]);
                acc[r] = fmaf(xv.z, w2, acc[r]);
                acc[r] = fmaf(xv.w, w3, acc[r]);
            }
        }
        const float bb = b1[t];
#pragma unroll
        for (int r = 0; r < 4; r++) h1s[r][t] = lrelu(acc[r] + bb);
    }
    __syncthreads();

    // ---- stage 2 (K-split): thread -> (col c of 128, k-half ks), 4 rows --
    {
        const int c = t & 127, ks = t >> 7;
        const int kb = ks * 128;
        float acc[4] = {0.f, 0.f, 0.f, 0.f};
#pragma unroll 16
        for (int k4 = 0; k4 < 128; k4 += 4) {
            const float w0 = W2[(kb + k4 + 0) * 128 + c];
            const float w1 = W2[(kb + k4 + 1) * 128 + c];
            const float w2 = W2[(kb + k4 + 2) * 128 + c];
            const float w3 = W2[(kb + k4 + 3) * 128 + c];
#pragma unroll
            for (int r = 0; r < 4; r++) {
                const float4 hv = *(const float4*)&h1s[r][kb + k4];
                acc[r] = fmaf(hv.x, w0, acc[r]);
                acc[r] = fmaf(hv.y, w1, acc[r]);
                acc[r] = fmaf(hv.z, w2, acc[r]);
                acc[r] = fmaf(hv.w, w3, acc[r]);
            }
        }
        if (ks == 1) {
#pragma unroll
            for (int r = 0; r < 4; r++) p2[r][c] = acc[r];
        }
        __syncthreads();
        if (ks == 0) {
            const float bb = b2[c];
            float s = 0.f, q = 0.f;
#pragma unroll
            for (int r = 0; r < 4; r++) {
                const float v = acc[r] + p2[r][c] + bb;
                g_h2[(r0 + r) * 128 + c] = v;
                s += v;
                q = fmaf(v, v, q);
            }
            atomicAdd(&g_sum[c], s);
            atomicAdd(&g_sq[c], q);
        }
    }
}

// ---- K3: BN+lrelu -> layer3 -> attention -> M (fp16, pre-scaled) --------
__global__ void __launch_bounds__(256, 2) k3_feat(const float* __restrict__ gamma,
                                                  const float* __restrict__ beta,
                                                  const float* __restrict__ W3,
                                                  const float* __restrict__ b3,
                                                  const float* __restrict__ Wv,
                                                  const float* __restrict__ bv,
                                                  const float* __restrict__ Wo,
                                                  const float* __restrict__ bo,
                                                  const float* __restrict__ T,
                                                  const float* __restrict__ Ws,
                                                  const float* __restrict__ bs,
                                                  float* __restrict__ out) {
    __shared__ float hb[8][128], h3s[8][64], avs[8][64], hhs[8][64];
    __shared__ float Mst[8][250];
    const int t  = threadIdx.x;
    const int r0 = blockIdx.x * 8;

#pragma unroll
    for (int qq = 0; qq < 4; qq++) {
        const int e = t + 256 * qq;
        const int r = e >> 7, c = e & 127;
        const float v   = g_h2[(r0 + r) * 128 + c];
        const float mu  = g_sum[c] * (1.f / BATCH);
        const float var = g_sq[c] * (1.f / BATCH) - mu * mu;
        const float rs  = rsqrtf(var + 1e-5f);
        hb[r][c] = lrelu(fmaf((v - mu) * rs, gamma[c], beta[c]));
    }
    __syncthreads();

    const int c  = t & 63;
    const int rg = t >> 6;               // 4 groups x 2 rows
    {
        float a0 = b3[c], a1 = a0;
#pragma unroll 16
        for (int k = 0; k < 128; k++) {
            const float w = W3[k * 64 + c];
            a0 = fmaf(hb[2 * rg][k], w, a0);
            a1 = fmaf(hb[2 * rg + 1][k], w, a1);
        }
        h3s[2 * rg][c] = lrelu(a0);
        h3s[2 * rg + 1][c] = lrelu(a1);
    }
    __syncthreads();
    {
        float a0 = bv[c], a1 = a0;
#pragma unroll 16
        for (int k = 0; k < 64; k++) {
            const float w = Wv[k * 64 + c];
            a0 = fmaf(h3s[2 * rg][k], w, a0);
            a1 = fmaf(h3s[2 * rg + 1][k], w, a1);
        }
        avs[2 * rg][c] = a0;
        avs[2 * rg + 1][c] = a1;
    }
    __syncthreads();
    {
        float a0 = bo[c] + h3s[2 * rg][c];
        float a1 = bo[c] + h3s[2 * rg + 1][c];
#pragma unroll 16
        for (int k = 0; k < 64; k++) {
            const float w = Wo[k * 64 + c];
            a0 = fmaf(avs[2 * rg][k], w, a0);
            a1 = fmaf(avs[2 * rg + 1][k], w, a1);
        }
        hhs[2 * rg][c] = a0;
        hhs[2 * rg + 1][c] = a1;
    }
    __syncthreads();

    {   // score base: one warp per row
        const int r = t >> 5, l = t & 31;
        float v = hhs[r][l] * Ws[l] + hhs[r][l + 32] * Ws[l + 32];
#pragma unroll
        for (int o = 16; o > 0; o >>= 1) v += __shfl_down_sync(0xffffffffu, v, o);
        if (l == 0) out[r0 + r] = v + bs[0];
    }

    if (t < 250) {                       // M = hh @ T (pre-scaled by log2 e)
        float acc[8];
#pragma unroll
        for (int r = 0; r < 8; r++) acc[r] = 0.f;
#pragma unroll 8
        for (int k = 0; k < 64; k++) {
            const float w = T[k * 250 + t];
#pragma unroll
            for (int r = 0; r < 8; r++) acc[r] = fmaf(hhs[r][k], w, acc[r]);
        }
#pragma unroll
        for (int r = 0; r < 8; r++) Mst[r][t] = acc[r] * LOG2E;
    }
    __syncthreads();

    for (int idx = t; idx < 400; idx += 256) {
        const int r = idx / 50, f = idx % 50;
        __half2 h01 = __floats2half2_rn(Mst[r][5 * f + 0], Mst[r][5 * f + 1]);
        __half2 h23 = __floats2half2_rn(Mst[r][5 * f + 2], Mst[r][5 * f + 3]);
        __half2 h4p = __floats2half2_rn(Mst[r][5 * f + 4], 0.f);
        uint4 v;
        v.x = *reinterpret_cast<const unsigned*>(&h01);
        v.y = *reinterpret_cast<const unsigned*>(&h23);
        v.z = *reinterpret_cast<const unsigned*>(&h4p);
        v.w = 0u;
        g_Mh[f * BATCH + r0 + r] = v;
    }
}

// ------- K4: MBD, symmetric pairs, fp16x2 v2 + vectorized LDS ------------
__global__ void __launch_bounds__(256) k4_mbd(const float* __restrict__ Ws,
                                              float* __restrict__ out) {
    __shared__ __align__(16) __half2 sA[10][5][64];  // (m,m) broadcast pairs
    __shared__ __align__(16) __half  sJ[10][5][64];  // plain halves by j
    __shared__ float red[16][132];

    const int t = threadIdx.x;
    int u = blockIdx.x, ti_s = 0;
    while (u >= 16 - ti_s) { u -= 16 - ti_s; ti_s++; }
    const int tj_s = ti_s + u;
    const int I0 = ti_s * 64, J0 = tj_s * 64;
    const bool diag = (ti_s == tj_s);
    const int ti = t >> 4, tj = t & 15;

    const uint4* __restrict__ Mh = g_Mh + blockIdx.y * 10 * BATCH;
    for (int idx = t; idx < 640; idx += 256) {
        const int ff = idx >> 6, r = idx & 63;
        const uint4 vI = Mh[ff * BATCH + I0 + r];
        const __half2 a01 = *reinterpret_cast<const __half2*>(&vI.x);
        const __half2 a23 = *reinterpret_cast<const __half2*>(&vI.y);
        const __half2 a4  = *reinterpret_cast<const __half2*>(&vI.z);
        sA[ff][0][r] = __half2half2(__low2half(a01));
        sA[ff][1][r] = __half2half2(__high2half(a01));
        sA[ff][2][r] = __half2half2(__low2half(a23));
        sA[ff][3][r] = __half2half2(__high2half(a23));
        sA[ff][4][r] = __half2half2(__low2half(a4));
        const uint4 vJ = Mh[ff * BATCH + J0 + r];
        const __half2 j01 = *reinterpret_cast<const __half2*>(&vJ.x);
        const __half2 j23 = *reinterpret_cast<const __half2*>(&vJ.y);
        const __half2 j4  = *reinterpret_cast<const __half2*>(&vJ.z);
        sJ[ff][0][r] = __low2half(j01);
        sJ[ff][1][r] = __high2half(j01);
        sJ[ff][2][r] = __low2half(j23);
        sJ[ff][3][r] = __high2half(j23);
        sJ[ff][4][r] = __low2half(j4);
    }
    __syncthreads();

    // diag lane masks: allowed iff local i > local j (I0 == J0 on diag)
    __half2 dmask[4][2];
#pragma unroll
    for (int a = 0; a < 4; a++)
#pragma unroll
        for (int bp = 0; bp < 2; bp++)
            dmask[a][bp] = __floats2half2_rn(
                (ti * 4 + a) > (tj * 4 + 2 * bp) ? 1.f : 0.f,
                (ti * 4 + a) > (tj * 4 + 2 * bp + 1) ? 1.f : 0.f);

    float raccW[4] = {0.f, 0.f, 0.f, 0.f};
    float caccW[4] = {0.f, 0.f, 0.f, 0.f};

#pragma unroll 1
    for (int ff = 0; ff < 10; ff++) {
        __half2 mA[4][5], mJ[2][5];
#pragma unroll
        for (int d = 0; d < 5; d++) {
            const uint4 va = *reinterpret_cast<const uint4*>(&sA[ff][d][ti * 4]);
            mA[0][d] = *reinterpret_cast<const __half2*>(&va.x);
            mA[1][d] = *reinterpret_cast<const __half2*>(&va.y);
            mA[2][d] = *reinterpret_cast<const __half2*>(&va.z);
            mA[3][d] = *reinterpret_cast<const __half2*>(&va.w);
            const uint2 vj = *reinterpret_cast<const uint2*>(&sJ[ff][d][tj * 4]);
            mJ[0][d] = *reinterpret_cast<const __half2*>(&vj.x);
            mJ[1][d] = *reinterpret_cast<const __half2*>(&vj.y);
        }

        __half2 racc2[4], cacc2[2];
#pragma unroll
        for (int a = 0; a < 4; a++) racc2[a] = __floats2half2_rn(0.f, 0.f);
#pragma unroll
        for (int bp = 0; bp < 2; bp++) cacc2[bp] = __floats2half2_rn(0.f, 0.f);

        if (!diag) {
#pragma unroll
            for (int a = 0; a < 4; a++) {
#pragma unroll
                for (int bp = 0; bp < 2; bp++) {
                    const __half2 d0 = __hsub2(mA[a][0], mJ[bp][0]);
                    const __half2 d1 = __hsub2(mA[a][1], mJ[bp][1]);
                    const __half2 d2 = __hsub2(mA[a][2], mJ[bp][2]);
                    const __half2 d3 = __hsub2(mA[a][3], mJ[bp][3]);
                    const __half2 d4 = __hsub2(mA[a][4], mJ[bp][4]);
                    __half2 s = __hadd2(__habs2(d0), __habs2(d1));
                    const __half2 s2 = __hadd2(__habs2(d2), __habs2(d3));
                    s = __hadd2(s, s2);
                    s = __hadd2(s, __habs2(d4));
                    const __half2 e = h2exp2(__hneg2(s));
                    racc2[a]  = __hadd2(racc2[a], e);
                    cacc2[bp] = __hadd2(cacc2[bp], e);
                }
            }
        } else {
#pragma unroll
            for (int a = 0; a < 4; a++) {
#pragma unroll
                for (int bp = 0; bp < 2; bp++) {
                    const __half2 d0 = __hsub2(mA[a][0], mJ[bp][0]);
                    const __half2 d1 = __hsub2(mA[a][1], mJ[bp][1]);
                    const __half2 d2 = __hsub2(mA[a][2], mJ[bp][2]);
                    const __half2 d3 = __hsub2(mA[a][3], mJ[bp][3]);
                    const __half2 d4 = __hsub2(mA[a][4], mJ[bp][4]);
                    __half2 s = __hadd2(__habs2(d0), __habs2(d1));
                    const __half2 s2 = __hadd2(__habs2(d2), __habs2(d3));
                    s = __hadd2(s, s2);
                    s = __hadd2(s, __habs2(d4));
                    __half2 e = h2exp2(__hneg2(s));
                    e = __hmul2(e, dmask[a][bp]);
                    racc2[a]  = __hadd2(racc2[a], e);
                    cacc2[bp] = __hadd2(cacc2[bp], e);
                }
            }
        }
        const float wf = Ws[64 + blockIdx.y * 10 + ff];
#pragma unroll
        for (int a = 0; a < 4; a++) {
            const float2 fr = __half22float2(racc2[a]);
            raccW[a] = fmaf(fr.x + fr.y, wf, raccW[a]);
        }
#pragma unroll
        for (int bp = 0; bp < 2; bp++) {
            const float2 fc = __half22float2(cacc2[bp]);
            caccW[2 * bp]     = fmaf(fc.x, wf, caccW[2 * bp]);
            caccW[2 * bp + 1] = fmaf(fc.y, wf, caccW[2 * bp + 1]);
        }
    }

    __syncthreads();
#pragma unroll
    for (int a = 0; a < 4; a++) red[tj][ti * 4 + a] = raccW[a];
#pragma unroll
    for (int b = 0; b < 4; b++) red[ti][64 + tj * 4 + b] = caccW[b];
    __syncthreads();

    if (t < 128) {
        float s = 0.f;
#pragma unroll
        for (int g = 0; g < 16; g++) s += red[g][t];
        const int target = (t < 64) ? (I0 + t) : (J0 + t - 64);
        atomicAdd(&out[target], s);
    }

    // re-zero BN stat accumulators for the NEXT graph replay (k4 is the
    // final node; next replay's k12 follows it in stream order).
    if (blockIdx.x == 0 && blockIdx.y == 0 && t < 128) {
        g_sum[t] = 0.f;
        g_sq[t]  = 0.f;
    }
}

// ---------------- launcher ----------------
extern "C" void kernel_launch(void* const* d_in, const int* in_sizes, int n_in,
                              void* d_out, int out_size) {
    const float* x     = (const float*)d_in[0];
    const float* W1    = (const float*)d_in[1];
    const float* b1    = (const float*)d_in[2];
    const float* W2    = (const float*)d_in[3];
    const float* b2    = (const float*)d_in[4];
    const float* gamma = (const float*)d_in[5];
    const float* beta  = (const float*)d_in[6];
    const float* W3    = (const float*)d_in[7];
    const float* b3    = (const float*)d_in[8];
    const float* Wv    = (const float*)d_in[9];
    const float* bv    = (const float*)d_in[10];
    const float* Wo    = (const float*)d_in[11];
    const float* bo    = (const float*)d_in[12];
    const float* T     = (const float*)d_in[13];
    const float* Ws    = (const float*)d_in[14];
    const float* bs    = (const float*)d_in[15];
    float* out = (float*)d_out;

    k12_gemm<<<256, 256>>>(x, W1, b1, W2, b2);
    k3_feat<<<128, 256>>>(gamma, beta, W3, b3, Wv, bv, Wo, bo, T, Ws, bs, out);
    k4_mbd<<<dim3(136, 5), 256>>>(Ws, out);
}